// round 1
// baseline (speedup 1.0000x reference)
#include <cuda_runtime.h>

// ---------------------------------------------------------------------------
// DualOrthogonalAttention, fused per-batch kernel (fp32 SIMT baseline)
// Shapes: BS=1024, S(node=region)=62, DIM=65, NHEADS=10
// Output: fused (1024,10,124,65) fp32 followed by orth_loss scalar.
// ---------------------------------------------------------------------------

#define BSZ 1024
#define S 62
#define DIM 65
#define H 10
#define LD 68        // row stride (floats) for DIM-wide smem buffers (even, float2 ok)
#define LDA 64       // row stride for 62-wide attention buffers
#define NTHREADS 512

// smem layout (float offsets)
#define SZ_F   (64 * LD)     // 4352
#define SZ_KT  (66 * LD)     // 4488 (rows indexed by k up to 64)
#define SZ_A   (64 * LDA)    // 4096
#define OFF_FN   0
#define OFF_FR   (OFF_FN + SZ_F)
#define OFF_Q    (OFF_FR + SZ_F)
#define OFF_KT   (OFF_Q + SZ_F)
#define OFF_W    (OFF_KT + SZ_KT)
#define OFF_A1   (OFF_W + SZ_KT)
#define OFF_A2   (OFF_A1 + SZ_A)
#define OFF_A2T  (OFF_A2 + SZ_A)
#define OFF_G    (OFF_A2T + SZ_A)
#define OFF_MEAN (OFF_G + 68)
#define OFF_WARP (OFF_MEAN + 132)
#define SMEM_FLOATS (OFF_WARP + 16 + 136)   // + tail pad for float2 overreads

__device__ float g_norms[BSZ * H];

#define EPI_ROW   0   // smem row-major store + bias
#define EPI_TRANS 1   // smem transposed store + bias
#define EPI_SCALE 2   // smem row-major store * scale
#define EPI_OUT   3   // global store * gate factor
#define EPI_LOSS  4   // accumulate ||C - I||^2 contribution

// C[M x N] = A[M x K] @ Bt  (Bt accessed as Bt[k*ldb + n])
// Mapping: warp w -> rows 4w..4w+3 ; lane l -> cols 2l, 2l+1 (+64 chunk for N=65)
template <int EPI>
__device__ __forceinline__ float gemm_tile(
    const float* __restrict__ A, int lda,
    const float* __restrict__ Bt, int ldb,
    int M, int N, int Kd,
    float* __restrict__ C, int ldc,
    const float* __restrict__ bias,
    float scale,
    float* __restrict__ gout,          // global, row stride DIM
    const float* __restrict__ g,
    bool one_minus)
{
    const int warp = threadIdx.x >> 5;
    const int lane = threadIdx.x & 31;
    const int r0 = warp << 2;
    float ss = 0.f;

    for (int jc = 0; jc < N; jc += 64) {
        const int j = jc + (lane << 1);
        if (j >= N) break;

        float acc[4][2];
#pragma unroll
        for (int rr = 0; rr < 4; rr++) { acc[rr][0] = 0.f; acc[rr][1] = 0.f; }

        const int K2 = Kd & ~1;
        int k = 0;
#pragma unroll 4
        for (; k < K2; k += 2) {
            const float2 b0 = *(const float2*)(Bt + k * ldb + j);
            const float2 b1 = *(const float2*)(Bt + (k + 1) * ldb + j);
#pragma unroll
            for (int rr = 0; rr < 4; rr++) {
                const float2 a = *(const float2*)(A + (r0 + rr) * lda + k);
                acc[rr][0] = fmaf(a.x, b0.x, acc[rr][0]);
                acc[rr][1] = fmaf(a.x, b0.y, acc[rr][1]);
                acc[rr][0] = fmaf(a.y, b1.x, acc[rr][0]);
                acc[rr][1] = fmaf(a.y, b1.y, acc[rr][1]);
            }
        }
        if (k < Kd) {
            const float2 b0 = *(const float2*)(Bt + k * ldb + j);
#pragma unroll
            for (int rr = 0; rr < 4; rr++) {
                const float a = A[(r0 + rr) * lda + k];
                acc[rr][0] = fmaf(a, b0.x, acc[rr][0]);
                acc[rr][1] = fmaf(a, b0.y, acc[rr][1]);
            }
        }

        const bool j1 = (j + 1 < N);
        float x0 = 0.f, x1 = 0.f;
        if (EPI == EPI_ROW || EPI == EPI_TRANS) {
            x0 = bias[j];
            x1 = j1 ? bias[j + 1] : 0.f;
        }
        if (EPI == EPI_OUT) {
            x0 = one_minus ? (1.f - g[j]) : g[j];
            x1 = j1 ? (one_minus ? (1.f - g[j + 1]) : g[j + 1]) : 0.f;
        }

#pragma unroll
        for (int rr = 0; rr < 4; rr++) {
            const int r = r0 + rr;
            if (r >= M) break;
            if (EPI == EPI_ROW) {
                C[r * ldc + j] = acc[rr][0] + x0;
                if (j1) C[r * ldc + j + 1] = acc[rr][1] + x1;
            } else if (EPI == EPI_TRANS) {
                C[j * ldc + r] = acc[rr][0] + x0;
                if (j1) C[(j + 1) * ldc + r] = acc[rr][1] + x1;
            } else if (EPI == EPI_SCALE) {
                C[r * ldc + j] = acc[rr][0] * scale;
                if (j1) C[r * ldc + j + 1] = acc[rr][1] * scale;
            } else if (EPI == EPI_OUT) {
                gout[r * DIM + j] = x0 * acc[rr][0];
                if (j1) gout[r * DIM + j + 1] = x1 * acc[rr][1];
            } else {  // EPI_LOSS
                float d0 = acc[rr][0] - ((r == j) ? 1.f : 0.f);
                ss = fmaf(d0, d0, ss);
                if (j1) {
                    float d1 = acc[rr][1] - ((r == j + 1) ? 1.f : 0.f);
                    ss = fmaf(d1, d1, ss);
                }
            }
        }
    }
    return ss;
}

// load a 65x65 weight head tile, transposed into sW[k*LD + j]
__device__ __forceinline__ void load_w(const float* __restrict__ W, float* __restrict__ sW) {
    for (int idx = threadIdx.x; idx < DIM * DIM; idx += NTHREADS) {
        const int jcol = idx / DIM;
        const int k = idx - jcol * DIM;
        sW[k * LD + jcol] = W[idx];
    }
}

// row softmax over 62 cols of a [62 x LDA] smem matrix; optional transposed copy
__device__ __forceinline__ void softmax62(float* __restrict__ Ssm, float* __restrict__ At) {
    const int warp = threadIdx.x >> 5;
    const int lane = threadIdx.x & 31;
    for (int r = warp; r < S; r += 16) {
        float* row = Ssm + r * LDA;
        float v0 = (lane < S) ? row[lane] : -1e30f;
        float v1 = (lane + 32 < S) ? row[lane + 32] : -1e30f;
        float m = fmaxf(v0, v1);
#pragma unroll
        for (int off = 16; off; off >>= 1) m = fmaxf(m, __shfl_xor_sync(0xffffffffu, m, off));
        float e0 = (lane < S) ? __expf(v0 - m) : 0.f;
        float e1 = (lane + 32 < S) ? __expf(v1 - m) : 0.f;
        float s = e0 + e1;
#pragma unroll
        for (int off = 16; off; off >>= 1) s += __shfl_xor_sync(0xffffffffu, s, off);
        const float inv = 1.0f / s;
        if (lane < S) {
            const float a = e0 * inv;
            row[lane] = a;
            if (At) At[lane * LDA + r] = a;
        }
        if (lane + 32 < S) {
            const float a = e1 * inv;
            row[lane + 32] = a;
            if (At) At[(lane + 32) * LDA + r] = a;
        }
    }
}

__global__ void __launch_bounds__(NTHREADS, 1)
fused_kernel(const float* __restrict__ Fn, const float* __restrict__ Fr,
             const float* __restrict__ Wq1, const float* __restrict__ bq1,
             const float* __restrict__ Wk1, const float* __restrict__ bk1,
             const float* __restrict__ Wq2, const float* __restrict__ bq2,
             const float* __restrict__ Wk2, const float* __restrict__ bk2,
             const float* __restrict__ Wg, const float* __restrict__ bg,
             float* __restrict__ out)
{
    extern __shared__ float sm[];
    const int tid = threadIdx.x;
    const int b = blockIdx.x;

    float* sFn = sm + OFF_FN;
    float* sFr = sm + OFF_FR;
    float* sQ = sm + OFF_Q;
    float* sKt = sm + OFF_KT;
    float* sW = sm + OFF_W;
    float* sA1 = sm + OFF_A1;
    float* sA2 = sm + OFF_A2;
    float* sA2t = sm + OFF_A2T;
    float* sg = sm + OFF_G;
    float* smean = sm + OFF_MEAN;
    float* swarp = sm + OFF_WARP;

    // load Fn, Fr tiles
    for (int idx = tid; idx < S * DIM; idx += NTHREADS) {
        const int i = idx / DIM;
        const int d = idx - i * DIM;
        sFn[i * LD + d] = Fn[(size_t)b * S * DIM + idx];
        sFr[i * LD + d] = Fr[(size_t)b * S * DIM + idx];
    }
    __syncthreads();

    // gate: g = sigmoid([mean(Fn); mean(Fr)] @ Wg^T + bg)
    for (int d = tid; d < 2 * DIM; d += NTHREADS) {
        const float* src = (d < DIM) ? sFn : sFr;
        const int dd = (d < DIM) ? d : d - DIM;
        float s = 0.f;
        for (int i = 0; i < S; i++) s += src[i * LD + dd];
        smean[d] = s * (1.0f / S);
    }
    __syncthreads();
    for (int o = tid; o < DIM; o += NTHREADS) {
        float acc = bg[o];
        const float* wr = Wg + o * 2 * DIM;
        for (int c = 0; c < 2 * DIM; c++) acc = fmaf(wr[c], smean[c], acc);
        sg[o] = 1.0f / (1.0f + __expf(-acc));
    }
    __syncthreads();

    const float scale = rsqrtf((float)DIM);

    for (int h = 0; h < H; h++) {
        const int woff = h * DIM * DIM;
        const int boff = h * DIM;

        // ---- direction 1: Q = Fn @ Wq1_h^T, K = Fr @ Wk1_h^T ----
        load_w(Wq1 + woff, sW);
        __syncthreads();
        gemm_tile<EPI_ROW>(sFn, LD, sW, LD, S, DIM, DIM, sQ, LD, bq1 + boff, 0.f, 0, 0, false);
        __syncthreads();
        load_w(Wk1 + woff, sW);
        __syncthreads();
        gemm_tile<EPI_TRANS>(sFr, LD, sW, LD, S, DIM, DIM, sKt, LD, bk1 + boff, 0.f, 0, 0, false);
        __syncthreads();
        gemm_tile<EPI_SCALE>(sQ, LD, sKt, LD, S, S, DIM, sA1, LDA, 0, scale, 0, 0, false);
        __syncthreads();
        softmax62(sA1, 0);
        __syncthreads();

        // ---- direction 2: Q = Fr @ Wq2_h^T, K = Fn @ Wk2_h^T ----
        load_w(Wq2 + woff, sW);
        __syncthreads();
        gemm_tile<EPI_ROW>(sFr, LD, sW, LD, S, DIM, DIM, sQ, LD, bq2 + boff, 0.f, 0, 0, false);
        __syncthreads();
        load_w(Wk2 + woff, sW);
        __syncthreads();
        gemm_tile<EPI_TRANS>(sFn, LD, sW, LD, S, DIM, DIM, sKt, LD, bk2 + boff, 0.f, 0, 0, false);
        __syncthreads();
        gemm_tile<EPI_SCALE>(sQ, LD, sKt, LD, S, S, DIM, sA2, LDA, 0, scale, 0, 0, false);
        __syncthreads();
        softmax62(sA2, sA2t);
        __syncthreads();

        // ---- orthogonality loss: C = A1 @ A2^T, ||C - I||_F ----
        float ss = gemm_tile<EPI_LOSS>(sA1, LDA, sA2t, LDA, S, S, S, 0, 0, 0, 0.f, 0, 0, false);
#pragma unroll
        for (int off = 16; off; off >>= 1) ss += __shfl_xor_sync(0xffffffffu, ss, off);
        if ((tid & 31) == 0) swarp[tid >> 5] = ss;
        __syncthreads();
        if (tid == 0) {
            float t = 0.f;
#pragma unroll
            for (int w = 0; w < 16; w++) t += swarp[w];
            g_norms[b * H + h] = sqrtf(t);
        }

        // ---- outputs: fused[b,h,0:62]   = g * (A1 @ Fr)
        //              fused[b,h,62:124] = (1-g) * (A2 @ Fn) ----
        float* o1 = out + ((size_t)(b * H + h) * 124) * DIM;
        float* o2 = o1 + (size_t)S * DIM;
        gemm_tile<EPI_OUT>(sA1, LDA, sFr, LD, S, DIM, S, 0, 0, 0, 0.f, o1, sg, false);
        gemm_tile<EPI_OUT>(sA2, LDA, sFn, LD, S, DIM, S, 0, 0, 0, 0.f, o2, sg, true);
        __syncthreads();
    }
}

__global__ void loss_kernel(float* __restrict__ out_loss)
{
    __shared__ float ws[8];
    const int tid = threadIdx.x;
    float s = 0.f;
    for (int i = tid; i < BSZ * H; i += 256) s += g_norms[i];
#pragma unroll
    for (int off = 16; off; off >>= 1) s += __shfl_xor_sync(0xffffffffu, s, off);
    if ((tid & 31) == 0) ws[tid >> 5] = s;
    __syncthreads();
    if (tid == 0) {
        float t = 0.f;
#pragma unroll
        for (int w = 0; w < 8; w++) t += ws[w];
        *out_loss = t / (float)(BSZ * H);
    }
}

extern "C" void kernel_launch(void* const* d_in, const int* in_sizes, int n_in,
                              void* d_out, int out_size)
{
    const float* Fn  = (const float*)d_in[0];
    const float* Fr  = (const float*)d_in[1];
    const float* Wq1 = (const float*)d_in[2];
    const float* bq1 = (const float*)d_in[3];
    const float* Wk1 = (const float*)d_in[4];
    const float* bk1 = (const float*)d_in[5];
    const float* Wq2 = (const float*)d_in[6];
    const float* bq2 = (const float*)d_in[7];
    const float* Wk2 = (const float*)d_in[8];
    const float* bk2 = (const float*)d_in[9];
    const float* Wg  = (const float*)d_in[10];
    const float* bg  = (const float*)d_in[11];
    float* out = (float*)d_out;

    const int smem_bytes = SMEM_FLOATS * (int)sizeof(float);
    cudaFuncSetAttribute(fused_kernel, cudaFuncAttributeMaxDynamicSharedMemorySize, smem_bytes);
    fused_kernel<<<BSZ, NTHREADS, smem_bytes>>>(Fn, Fr, Wq1, bq1, Wk1, bk1,
                                                Wq2, bq2, Wk2, bk2, Wg, bg, out);
    loss_kernel<<<1, 256>>>(out + (size_t)out_size - 1);
}

// round 3
// speedup vs baseline: 1.3329x; 1.3329x over previous
#include <cuda_runtime.h>
#include <cstdint>

// ---------------------------------------------------------------------------
// DualOrthogonalAttention fused kernel, round 3 (= round 2 + cstdint fix).
// All GEMMs use N=62 on lanes (2 cols/lane, lane31 idle) and put the ragged
// 65-dim on warp-distributed rows (warp-uniform skip). Weights stream in via
// double-buffered cp.async. Outputs staged transposed in smem, copied
// coalesced with the gate applied.
// ---------------------------------------------------------------------------

#define BSZ 1024
#define S 62
#define DIM 65
#define H 10
#define NT 512

#define LDF 68    // sFn,sFr row-major [62 x 65]
#define LDT 66    // sFnT,sFrT        [65 x 62]
#define LDQ 64    // Qt,Kt [65 x 62], sS [62 x 62]
#define LDA1 66   // A1t,A2t          [62 x 62]
#define LDO 66    // sO1,sO2          [65 x 62]
#define LDW 66    // sW               [65 x 65] (+3 pad rows for overreads)

#define OFF_SFN  0
#define OFF_SFR  (OFF_SFN + S*LDF)
#define OFF_SFNT (OFF_SFR + S*LDF)
#define OFF_SFRT (OFF_SFNT + DIM*LDT)
#define OFF_QT   (OFF_SFRT + DIM*LDT)
#define OFF_KT   (OFF_QT + DIM*LDQ)
#define OFF_SS   (OFF_KT + DIM*LDQ)
#define OFF_A1T  (OFF_SS + S*LDQ)
#define OFF_A2T  (OFF_A1T + S*LDA1)
#define OFF_O1   (OFF_A2T + S*LDA1)
#define OFF_O2   (OFF_O1 + DIM*LDO)
#define OFF_W0   (OFF_O2 + DIM*LDO)
#define OFF_W1   (OFF_W0 + 68*LDW)
#define OFF_G    (OFF_W1 + 68*LDW)
#define OFF_MEAN (OFF_G + 68)
#define OFF_WARP (OFF_MEAN + 132)
#define SMEM_FLOATS (OFF_WARP + 32)

__device__ float g_norms[BSZ * H];

// ---------------------------------------------------------------------------
// cp.async helpers
// ---------------------------------------------------------------------------
__device__ __forceinline__ void cp_async4(uint32_t dst, const float* src) {
    asm volatile("cp.async.ca.shared.global [%0], [%1], 4;\n" :: "r"(dst), "l"(src));
}
__device__ __forceinline__ void cp_commit() {
    asm volatile("cp.async.commit_group;\n" ::);
}
__device__ __forceinline__ void cp_wait0() {
    asm volatile("cp.async.wait_group 0;\n" ::);
}

// stream one 65x65 head-weight tile into smem rows of stride LDW
__device__ __forceinline__ void prefetch_w(const float* __restrict__ gW, float* sW) {
    uint32_t base = (uint32_t)__cvta_generic_to_shared(sW);
    for (int idx = threadIdx.x; idx < DIM * DIM; idx += NT) {
        const int row = idx / DIM;
        const int col = idx - row * DIM;
        cp_async4(base + (uint32_t)(row * LDW + col) * 4u, gW + idx);
    }
    cp_commit();
}

// ---------------------------------------------------------------------------
// Generic block GEMM: C[m,n] = sum_k a(m,k) * Bt[k*ldb + n], N == 62.
// Warp w handles rows 4w..4w+3 (+64 per extra pass for M=65); lane l handles
// cols 2l, 2l+1 (lane 31 idle). AKM: A stored k-major (A[k*lda + m]),
// otherwise row-major (A[m*lda + k]). All strides even -> float2 everywhere.
// ---------------------------------------------------------------------------
#define EPI_BIASR 0   // C = acc + bias[m]
#define EPI_SCALE 1   // C = acc * scale
#define EPI_PLAIN 2   // C = acc
#define EPI_LOSS  3   // ss += (acc - I[m,j])^2, nothing stored

template <int EPI, bool AKM>
__device__ __forceinline__ float gemm62(
    const float* __restrict__ A, const int lda,
    const float* __restrict__ Bt, const int ldb,
    const int M, const int Kd,
    float* __restrict__ C, const int ldc,
    const float* __restrict__ bias, const float scale)
{
    const int warp = threadIdx.x >> 5;
    const int lane = threadIdx.x & 31;
    const int j = lane << 1;
    const bool jok = (j < S);
    float ss = 0.f;

    for (int r0 = warp << 2; r0 < M; r0 += 64) {
        float a00 = 0.f, a01 = 0.f, a10 = 0.f, a11 = 0.f;
        float a20 = 0.f, a21 = 0.f, a30 = 0.f, a31 = 0.f;
        if (jok) {
            const int K2 = Kd & ~1;
            int k = 0;
#pragma unroll 4
            for (; k < K2; k += 2) {
                const float2 b0 = *(const float2*)(Bt + k * ldb + j);
                const float2 b1 = *(const float2*)(Bt + (k + 1) * ldb + j);
                float x0, x1, x2, x3, y0, y1, y2, y3;
                if (AKM) {
                    const float2 p = *(const float2*)(A + k * lda + r0);
                    const float2 q = *(const float2*)(A + k * lda + r0 + 2);
                    const float2 u = *(const float2*)(A + (k + 1) * lda + r0);
                    const float2 v = *(const float2*)(A + (k + 1) * lda + r0 + 2);
                    x0 = p.x; x1 = p.y; x2 = q.x; x3 = q.y;
                    y0 = u.x; y1 = u.y; y2 = v.x; y3 = v.y;
                } else {
                    const float2 p0 = *(const float2*)(A + (r0 + 0) * lda + k);
                    const float2 p1 = *(const float2*)(A + (r0 + 1) * lda + k);
                    const float2 p2 = *(const float2*)(A + (r0 + 2) * lda + k);
                    const float2 p3 = *(const float2*)(A + (r0 + 3) * lda + k);
                    x0 = p0.x; y0 = p0.y; x1 = p1.x; y1 = p1.y;
                    x2 = p2.x; y2 = p2.y; x3 = p3.x; y3 = p3.y;
                }
                a00 = fmaf(x0, b0.x, a00); a01 = fmaf(x0, b0.y, a01);
                a10 = fmaf(x1, b0.x, a10); a11 = fmaf(x1, b0.y, a11);
                a20 = fmaf(x2, b0.x, a20); a21 = fmaf(x2, b0.y, a21);
                a30 = fmaf(x3, b0.x, a30); a31 = fmaf(x3, b0.y, a31);
                a00 = fmaf(y0, b1.x, a00); a01 = fmaf(y0, b1.y, a01);
                a10 = fmaf(y1, b1.x, a10); a11 = fmaf(y1, b1.y, a11);
                a20 = fmaf(y2, b1.x, a20); a21 = fmaf(y2, b1.y, a21);
                a30 = fmaf(y3, b1.x, a30); a31 = fmaf(y3, b1.y, a31);
            }
            if (k < Kd) {
                const float2 b0 = *(const float2*)(Bt + k * ldb + j);
                float x0, x1, x2, x3;
                if (AKM) {
                    const float2 p = *(const float2*)(A + k * lda + r0);
                    const float2 q = *(const float2*)(A + k * lda + r0 + 2);
                    x0 = p.x; x1 = p.y; x2 = q.x; x3 = q.y;
                } else {
                    x0 = A[(r0 + 0) * lda + k]; x1 = A[(r0 + 1) * lda + k];
                    x2 = A[(r0 + 2) * lda + k]; x3 = A[(r0 + 3) * lda + k];
                }
                a00 = fmaf(x0, b0.x, a00); a01 = fmaf(x0, b0.y, a01);
                a10 = fmaf(x1, b0.x, a10); a11 = fmaf(x1, b0.y, a11);
                a20 = fmaf(x2, b0.x, a20); a21 = fmaf(x2, b0.y, a21);
                a30 = fmaf(x3, b0.x, a30); a31 = fmaf(x3, b0.y, a31);
            }

#define DO_ROW(rr, v0, v1)                                                      \
            {                                                                   \
                const int m = r0 + rr;                                          \
                if (m < M) {                                                    \
                    if (EPI == EPI_BIASR) {                                     \
                        const float bb = bias[m];                               \
                        *(float2*)(C + m * ldc + j) = make_float2(v0 + bb, v1 + bb); \
                    } else if (EPI == EPI_SCALE) {                              \
                        *(float2*)(C + m * ldc + j) = make_float2(v0 * scale, v1 * scale); \
                    } else if (EPI == EPI_PLAIN) {                              \
                        *(float2*)(C + m * ldc + j) = make_float2(v0, v1);      \
                    } else {                                                    \
                        const float d0 = v0 - ((m == j) ? 1.f : 0.f);           \
                        const float d1 = v1 - ((m == j + 1) ? 1.f : 0.f);       \
                        ss = fmaf(d0, d0, ss); ss = fmaf(d1, d1, ss);           \
                    }                                                           \
                }                                                               \
            }
            DO_ROW(0, a00, a01)
            DO_ROW(1, a10, a11)
            DO_ROW(2, a20, a21)
            DO_ROW(3, a30, a31)
#undef DO_ROW
        }
    }
    return ss;
}

// row softmax over sS[62 x LDQ]; writes ONLY the transposed result At[LDA1]
__device__ __forceinline__ void softmax62t(const float* __restrict__ sS,
                                           float* __restrict__ At) {
    const int warp = threadIdx.x >> 5;
    const int lane = threadIdx.x & 31;
    for (int r = warp; r < S; r += 16) {
        const float* row = sS + r * LDQ;
        const float v0 = (lane < S) ? row[lane] : -1e30f;
        const float v1 = (lane + 32 < S) ? row[lane + 32] : -1e30f;
        float m = fmaxf(v0, v1);
#pragma unroll
        for (int off = 16; off; off >>= 1) m = fmaxf(m, __shfl_xor_sync(0xffffffffu, m, off));
        const float e0 = (lane < S) ? __expf(v0 - m) : 0.f;
        const float e1 = (lane + 32 < S) ? __expf(v1 - m) : 0.f;
        float s = e0 + e1;
#pragma unroll
        for (int off = 16; off; off >>= 1) s += __shfl_xor_sync(0xffffffffu, s, off);
        const float inv = 1.0f / s;
        if (lane < S) At[lane * LDA1 + r] = e0 * inv;
        if (lane + 32 < S) At[(lane + 32) * LDA1 + r] = e1 * inv;
    }
}

// copy transposed out tile [d, n] -> global [n, d], applying the gate
__device__ __forceinline__ void copy_out(const float* __restrict__ sO,
                                         const float* __restrict__ sg,
                                         float* __restrict__ gout, bool om) {
    for (int idx = threadIdx.x; idx < S * DIM; idx += NT) {
        const int n = idx / DIM;
        const int d = idx - n * DIM;
        float gv = sg[d];
        if (om) gv = 1.f - gv;
        gout[idx] = gv * sO[d * LDO + n];
    }
}

__global__ void __launch_bounds__(NT, 1)
fused_kernel(const float* __restrict__ Fn, const float* __restrict__ Fr,
             const float* __restrict__ Wq1, const float* __restrict__ bq1,
             const float* __restrict__ Wk1, const float* __restrict__ bk1,
             const float* __restrict__ Wq2, const float* __restrict__ bq2,
             const float* __restrict__ Wk2, const float* __restrict__ bk2,
             const float* __restrict__ Wg, const float* __restrict__ bg,
             float* __restrict__ out)
{
    extern __shared__ float sm[];
    const int tid = threadIdx.x;
    const int b = blockIdx.x;

    float* sFn  = sm + OFF_SFN;
    float* sFr  = sm + OFF_SFR;
    float* sFnT = sm + OFF_SFNT;
    float* sFrT = sm + OFF_SFRT;
    float* sQt  = sm + OFF_QT;
    float* sKt  = sm + OFF_KT;
    float* sS   = sm + OFF_SS;
    float* sA1t = sm + OFF_A1T;
    float* sA2t = sm + OFF_A2T;
    float* sO1  = sm + OFF_O1;
    float* sO2  = sm + OFF_O2;
    float* sWb[2] = { sm + OFF_W0, sm + OFF_W1 };
    float* sg   = sm + OFF_G;
    float* smean = sm + OFF_MEAN;
    float* swarp = sm + OFF_WARP;

    const float* wlist[4] = { Wq1, Wk1, Wq2, Wk2 };

    // kick off the first weight prefetch immediately
    prefetch_w(Wq1, sWb[0]);

    // load Fn/Fr into both layouts; stage Wg into sO1/sO2 region (contiguous)
    for (int idx = tid; idx < S * DIM; idx += NT) {
        const int i = idx / DIM;
        const int d = idx - i * DIM;
        const float vn = Fn[(size_t)b * S * DIM + idx];
        const float vr = Fr[(size_t)b * S * DIM + idx];
        sFn[i * LDF + d]  = vn;
        sFnT[d * LDT + i] = vn;
        sFr[i * LDF + d]  = vr;
        sFrT[d * LDT + i] = vr;
    }
    float* sWg = sO1;  // 8450 floats fit in sO1+sO2 (8580)
    for (int idx = tid; idx < 2 * DIM * DIM; idx += NT) sWg[idx] = Wg[idx];
    __syncthreads();

    // gate
    for (int idx = tid; idx < 2 * DIM; idx += NT) {
        const float* src = (idx < DIM) ? sFnT : sFrT;
        const int d = (idx < DIM) ? idx : idx - DIM;
        float s = 0.f;
        for (int i = 0; i < S; i++) s += src[d * LDT + i];
        smean[idx] = s * (1.0f / (float)S);
    }
    __syncthreads();
    for (int o = tid; o < DIM; o += NT) {
        float acc = bg[o];
        const float* wr = sWg + o * 2 * DIM;
        for (int c = 0; c < 2 * DIM; c++) acc = fmaf(wr[c], smean[c], acc);
        sg[o] = 1.0f / (1.0f + __expf(-acc));
    }
    // no sync needed here: first W-phase below starts with cp_wait0+sync

    const float scale = rsqrtf((float)DIM);

    for (int h = 0; h < H; h++) {
        const int i0 = 4 * h;
        const int boff = h * DIM;

#define W_PHASE(ii, BOP, OUT, BIAS)                                            \
        {                                                                      \
            cp_wait0();                                                        \
            __syncthreads();                                                   \
            const int nx = (ii) + 1;                                           \
            if (nx < 4 * H)                                                    \
                prefetch_w(wlist[nx & 3] + (nx >> 2) * DIM * DIM, sWb[nx & 1]);\
            gemm62<EPI_BIASR, false>(sWb[(ii) & 1], LDW, BOP, LDT, DIM, DIM,   \
                                     OUT, LDQ, BIAS, 0.f);                     \
            __syncthreads();                                                   \
        }

        // direction 1: Qt = Wq1 @ FnT, Kt = Wk1 @ FrT
        W_PHASE(i0 + 0, sFnT, sQt, bq1 + boff)
        W_PHASE(i0 + 1, sFrT, sKt, bk1 + boff)
        gemm62<EPI_SCALE, true>(sQt, LDQ, sKt, LDQ, S, DIM, sS, LDQ, 0, scale);
        __syncthreads();
        softmax62t(sS, sA1t);
        __syncthreads();

        // direction 2: Qt = Wq2 @ FrT, Kt = Wk2 @ FnT
        W_PHASE(i0 + 2, sFrT, sQt, bq2 + boff)
        W_PHASE(i0 + 3, sFnT, sKt, bk2 + boff)
        gemm62<EPI_SCALE, true>(sQt, LDQ, sKt, LDQ, S, DIM, sS, LDQ, 0, scale);
        __syncthreads();
        softmax62t(sS, sA2t);
        __syncthreads();
#undef W_PHASE

        // orth loss: C = A1 @ A2^T via A1t, A2t
        float ss = gemm62<EPI_LOSS, true>(sA1t, LDA1, sA2t, LDA1, S, S, 0, 0, 0, 0.f);
        // out_nT[d,n] = sum_r Fr[r,d] * A1t[r,n]; out_rT[d,r] = sum_n Fn[n,d] * A2t[n,r]
        gemm62<EPI_PLAIN, true>(sFr, LDF, sA1t, LDA1, DIM, S, sO1, LDO, 0, 0.f);
        gemm62<EPI_PLAIN, true>(sFn, LDF, sA2t, LDA1, DIM, S, sO2, LDO, 0, 0.f);

#pragma unroll
        for (int off = 16; off; off >>= 1) ss += __shfl_xor_sync(0xffffffffu, ss, off);
        if ((tid & 31) == 0) swarp[tid >> 5] = ss;
        __syncthreads();

        float* o1 = out + ((size_t)(b * H + h) * 124) * DIM;
        float* o2 = o1 + (size_t)S * DIM;
        copy_out(sO1, sg, o1, false);
        copy_out(sO2, sg, o2, true);
        if (tid == 0) {
            float t = 0.f;
#pragma unroll
            for (int w = 0; w < 16; w++) t += swarp[w];
            g_norms[b * H + h] = sqrtf(t);
        }
        __syncthreads();
    }
}

__global__ void loss_kernel(float* __restrict__ out_loss)
{
    __shared__ float ws[8];
    const int tid = threadIdx.x;
    float s = 0.f;
    for (int i = tid; i < BSZ * H; i += 256) s += g_norms[i];
#pragma unroll
    for (int off = 16; off; off >>= 1) s += __shfl_xor_sync(0xffffffffu, s, off);
    if ((tid & 31) == 0) ws[tid >> 5] = s;
    __syncthreads();
    if (tid == 0) {
        float t = 0.f;
#pragma unroll
        for (int w = 0; w < 8; w++) t += ws[w];
        *out_loss = t / (float)(BSZ * H);
    }
}

extern "C" void kernel_launch(void* const* d_in, const int* in_sizes, int n_in,
                              void* d_out, int out_size)
{
    const float* Fn  = (const float*)d_in[0];
    const float* Fr  = (const float*)d_in[1];
    const float* Wq1 = (const float*)d_in[2];
    const float* bq1 = (const float*)d_in[3];
    const float* Wk1 = (const float*)d_in[4];
    const float* bk1 = (const float*)d_in[5];
    const float* Wq2 = (const float*)d_in[6];
    const float* bq2 = (const float*)d_in[7];
    const float* Wk2 = (const float*)d_in[8];
    const float* bk2 = (const float*)d_in[9];
    const float* Wg  = (const float*)d_in[10];
    const float* bg  = (const float*)d_in[11];
    float* out = (float*)d_out;

    const int smem_bytes = SMEM_FLOATS * (int)sizeof(float);
    cudaFuncSetAttribute(fused_kernel, cudaFuncAttributeMaxDynamicSharedMemorySize, smem_bytes);
    fused_kernel<<<BSZ, NT, smem_bytes>>>(Fn, Fr, Wq1, bq1, Wk1, bk1,
                                          Wq2, bq2, Wk2, bk2, Wg, bg, out);
    loss_kernel<<<1, 256>>>(out + (size_t)out_size - 1);
}

// round 4
// speedup vs baseline: 1.4030x; 1.0526x over previous
#include <cuda_runtime.h>
#include <cstdint>

// ---------------------------------------------------------------------------
// DualOrthogonalAttention fused kernel, round 4.
// - Balanced M=65 row split: warps 0-14 take 4 rows, warp 15 takes 5 (no
//   serial second pass).
// - Merged projection phases, 8 syncs/head (was 14), 4-buffer weight pipeline.
// - sO1/sO2 alias sQt/sKt (disjoint lifetimes) to fit 4 weight buffers.
// ---------------------------------------------------------------------------

#define BSZ 1024
#define S 62
#define DIM 65
#define H 10
#define NT 512

#define LDF 68    // sFn,sFr row-major [62 x 65]
#define LDT 66    // sFnT,sFrT        [65 x 62]
#define LDQ 64    // Qt,Kt,sS,sO
#define LDA1 66   // A1t,A2t          [62 x 62]
#define LDW 66    // W                [65 x 65]

#define OFF_SFN  0
#define OFF_SFR  (OFF_SFN + S*LDF)         // 4216
#define OFF_SFNT (OFF_SFR + S*LDF)         // 8432
#define OFF_SFRT (OFF_SFNT + DIM*LDT)      // 12722
#define OFF_QT   (OFF_SFRT + DIM*LDT)      // 17012  (also sO1)
#define OFF_KT   (OFF_QT + DIM*LDQ)        // 21172  (also sO2)
#define OFF_SS   (OFF_KT + DIM*LDQ)        // 25332
#define OFF_A1T  (OFF_SS + S*LDQ)          // 29300
#define OFF_A2T  (OFF_A1T + S*LDA1)        // 33392
#define OFF_W0   (OFF_A2T + S*LDA1)        // 37484
#define OFF_W1   (OFF_W0 + DIM*LDW)        // 41774
#define OFF_W2   (OFF_W1 + DIM*LDW)        // 46064
#define OFF_W3   (OFF_W2 + DIM*LDW)        // 50354
#define OFF_G    (OFF_W3 + DIM*LDW)        // 54644
#define OFF_MEAN (OFF_G + 68)              // 54712
#define OFF_WARP (OFF_MEAN + 132)          // 54844
#define SMEM_FLOATS (OFF_WARP + 20)        // 54864 -> 214.3 KB

__device__ float g_norms[BSZ * H];

// ---------------------------------------------------------------------------
__device__ __forceinline__ void cp_async4(uint32_t dst, const float* src) {
    asm volatile("cp.async.ca.shared.global [%0], [%1], 4;\n" :: "r"(dst), "l"(src));
}
__device__ __forceinline__ void cp_commit() {
    asm volatile("cp.async.commit_group;\n" ::);
}
__device__ __forceinline__ void cp_wait0() {
    asm volatile("cp.async.wait_group 0;\n" ::);
}

__device__ __forceinline__ void prefetch_w(const float* __restrict__ gW, float* sW) {
    uint32_t base = (uint32_t)__cvta_generic_to_shared(sW);
    for (int idx = threadIdx.x; idx < DIM * DIM; idx += NT) {
        const int row = idx / DIM;
        const int col = idx - row * DIM;
        cp_async4(base + (uint32_t)(row * LDW + col) * 4u, gW + idx);
    }
    cp_commit();
}

// ---------------------------------------------------------------------------
// C[m,n] = sum_k a(m,k) * Bt[k*ldb + n], n in [0,62).
// One warp computes NR rows starting at r0; lane l -> cols 2l, 2l+1 (lane 31
// idle). AKM: A stored k-major (A[k*lda + m]); else row-major.
// ---------------------------------------------------------------------------
#define EPI_BIASR 0
#define EPI_SCALE 1
#define EPI_PLAIN 2
#define EPI_LOSS  3

template <int EPI, bool AKM, int NR>
__device__ __forceinline__ float gemm_body(
    const float* __restrict__ A, const int lda,
    const float* __restrict__ Bt, const int ldb,
    const int r0, const int M, const int Kd,
    float* __restrict__ C, const int ldc,
    const float* __restrict__ bias, const float scale)
{
    const int lane = threadIdx.x & 31;
    const int j = lane << 1;
    float ss = 0.f;
    if (j >= S) return 0.f;

    float acc[NR][2];
#pragma unroll
    for (int i = 0; i < NR; i++) { acc[i][0] = 0.f; acc[i][1] = 0.f; }

    const int K2 = Kd & ~1;
    int k = 0;
#pragma unroll 4
    for (; k < K2; k += 2) {
        const float2 b0 = *(const float2*)(Bt + k * ldb + j);
        const float2 b1 = *(const float2*)(Bt + (k + 1) * ldb + j);
        float xa[NR], ya[NR];
        if (AKM) {
            const float* Ak  = A + k * lda + r0;
            const float* Ak1 = Ak + lda;
#pragma unroll
            for (int i = 0; i < NR / 2; i++) {
                const float2 p = *(const float2*)(Ak + 2 * i);
                const float2 u = *(const float2*)(Ak1 + 2 * i);
                xa[2 * i] = p.x; xa[2 * i + 1] = p.y;
                ya[2 * i] = u.x; ya[2 * i + 1] = u.y;
            }
            if (NR & 1) { xa[NR - 1] = Ak[NR - 1]; ya[NR - 1] = Ak1[NR - 1]; }
        } else {
#pragma unroll
            for (int i = 0; i < NR; i++) {
                const float2 p = *(const float2*)(A + (r0 + i) * lda + k);
                xa[i] = p.x; ya[i] = p.y;
            }
        }
#pragma unroll
        for (int i = 0; i < NR; i++) {
            acc[i][0] = fmaf(xa[i], b0.x, acc[i][0]);
            acc[i][1] = fmaf(xa[i], b0.y, acc[i][1]);
            acc[i][0] = fmaf(ya[i], b1.x, acc[i][0]);
            acc[i][1] = fmaf(ya[i], b1.y, acc[i][1]);
        }
    }
    if (k < Kd) {
        const float2 b0 = *(const float2*)(Bt + k * ldb + j);
#pragma unroll
        for (int i = 0; i < NR; i++) {
            const float x = AKM ? A[k * lda + r0 + i] : A[(r0 + i) * lda + k];
            acc[i][0] = fmaf(x, b0.x, acc[i][0]);
            acc[i][1] = fmaf(x, b0.y, acc[i][1]);
        }
    }

#pragma unroll
    for (int i = 0; i < NR; i++) {
        const int m = r0 + i;
        if (m < M) {
            if (EPI == EPI_BIASR) {
                const float bb = bias[m];
                *(float2*)(C + m * ldc + j) = make_float2(acc[i][0] + bb, acc[i][1] + bb);
            } else if (EPI == EPI_SCALE) {
                *(float2*)(C + m * ldc + j) = make_float2(acc[i][0] * scale, acc[i][1] * scale);
            } else if (EPI == EPI_PLAIN) {
                *(float2*)(C + m * ldc + j) = make_float2(acc[i][0], acc[i][1]);
            } else {
                const float d0 = acc[i][0] - ((m == j) ? 1.f : 0.f);
                const float d1 = acc[i][1] - ((m == j + 1) ? 1.f : 0.f);
                ss = fmaf(d0, d0, ss); ss = fmaf(d1, d1, ss);
            }
        }
    }
    return ss;
}

template <int EPI, bool AKM>
__device__ __forceinline__ float gemm62(
    const float* __restrict__ A, const int lda,
    const float* __restrict__ Bt, const int ldb,
    const int M, const int Kd,
    float* __restrict__ C, const int ldc,
    const float* __restrict__ bias, const float scale)
{
    const int warp = threadIdx.x >> 5;
    if (M == DIM && warp == 15)
        return gemm_body<EPI, AKM, 5>(A, lda, Bt, ldb, 60, M, Kd, C, ldc, bias, scale);
    return gemm_body<EPI, AKM, 4>(A, lda, Bt, ldb, warp << 2, M, Kd, C, ldc, bias, scale);
}

// row softmax over sS[62 x LDQ]; writes transposed result At (stride LDA1)
__device__ __forceinline__ void softmax62t(const float* __restrict__ sS,
                                           float* __restrict__ At) {
    const int warp = threadIdx.x >> 5;
    const int lane = threadIdx.x & 31;
    for (int r = warp; r < S; r += 16) {
        const float* row = sS + r * LDQ;
        const float v0 = (lane < S) ? row[lane] : -1e30f;
        const float v1 = (lane + 32 < S) ? row[lane + 32] : -1e30f;
        float m = fmaxf(v0, v1);
#pragma unroll
        for (int off = 16; off; off >>= 1) m = fmaxf(m, __shfl_xor_sync(0xffffffffu, m, off));
        const float e0 = (lane < S) ? __expf(v0 - m) : 0.f;
        const float e1 = (lane + 32 < S) ? __expf(v1 - m) : 0.f;
        float s = e0 + e1;
#pragma unroll
        for (int off = 16; off; off >>= 1) s += __shfl_xor_sync(0xffffffffu, s, off);
        const float inv = 1.0f / s;
        if (lane < S) At[lane * LDA1 + r] = e0 * inv;
        if (lane + 32 < S) At[(lane + 32) * LDA1 + r] = e1 * inv;
    }
}

__device__ __forceinline__ void copy_out(const float* __restrict__ sO,
                                         const float* __restrict__ sg,
                                         float* __restrict__ gout, bool om) {
    for (int idx = threadIdx.x; idx < S * DIM; idx += NT) {
        const int n = idx / DIM;
        const int d = idx - n * DIM;
        float gv = sg[d];
        if (om) gv = 1.f - gv;
        gout[idx] = gv * sO[d * LDQ + n];
    }
}

__global__ void __launch_bounds__(NT, 1)
fused_kernel(const float* __restrict__ Fn, const float* __restrict__ Fr,
             const float* __restrict__ Wq1, const float* __restrict__ bq1,
             const float* __restrict__ Wk1, const float* __restrict__ bk1,
             const float* __restrict__ Wq2, const float* __restrict__ bq2,
             const float* __restrict__ Wk2, const float* __restrict__ bk2,
             const float* __restrict__ Wg, const float* __restrict__ bg,
             float* __restrict__ out)
{
    extern __shared__ float sm[];
    const int tid = threadIdx.x;
    const int b = blockIdx.x;

    float* sFn  = sm + OFF_SFN;
    float* sFr  = sm + OFF_SFR;
    float* sFnT = sm + OFF_SFNT;
    float* sFrT = sm + OFF_SFRT;
    float* sQt  = sm + OFF_QT;    // aliases sO1
    float* sKt  = sm + OFF_KT;    // aliases sO2
    float* sS   = sm + OFF_SS;
    float* sA1t = sm + OFF_A1T;
    float* sA2t = sm + OFF_A2T;
    float* sW0  = sm + OFF_W0;
    float* sW1  = sm + OFF_W1;
    float* sW2  = sm + OFF_W2;
    float* sW3  = sm + OFF_W3;
    float* sg   = sm + OFF_G;
    float* smean = sm + OFF_MEAN;
    float* swarp = sm + OFF_WARP;

    // prefetch head-0 direction-1 weights immediately
    prefetch_w(Wq1, sW0);
    prefetch_w(Wk1, sW1);

    // load Fn/Fr into both layouts
    for (int idx = tid; idx < S * DIM; idx += NT) {
        const int i = idx / DIM;
        const int d = idx - i * DIM;
        const float vn = Fn[(size_t)b * S * DIM + idx];
        const float vr = Fr[(size_t)b * S * DIM + idx];
        sFn[i * LDF + d]  = vn;
        sFnT[d * LDT + i] = vn;
        sFr[i * LDF + d]  = vr;
        sFrT[d * LDT + i] = vr;
    }
    __syncthreads();

    // gate
    for (int idx = tid; idx < 2 * DIM; idx += NT) {
        const float* src = (idx < DIM) ? sFnT : sFrT;
        const int d = (idx < DIM) ? idx : idx - DIM;
        float s = 0.f;
        for (int i = 0; i < S; i++) s += src[d * LDT + i];
        smean[idx] = s * (1.0f / (float)S);
    }
    __syncthreads();
    for (int o = tid; o < DIM; o += NT) {
        float acc = bg[o];
        const float* wr = Wg + o * 2 * DIM;
#pragma unroll 10
        for (int c = 0; c < 2 * DIM; c++) acc = fmaf(wr[c], smean[c], acc);
        sg[o] = 1.0f / (1.0f + __expf(-acc));
    }
    // sg read only after several later barriers

    const float scale = rsqrtf((float)DIM);

    for (int h = 0; h < H; h++) {
        const int woff = h * DIM * DIM;
        const int boff = h * DIM;

        // step1: direction-1 weights ready (also guards sQt/sKt reuse)
        cp_wait0();
        __syncthreads();

        // step2: prefetch dir2(h); both dir1 projections
        prefetch_w(Wq2 + woff, sW2);
        prefetch_w(Wk2 + woff, sW3);
        gemm62<EPI_BIASR, false>(sW0, LDW, sFnT, LDT, DIM, DIM, sQt, LDQ, bq1 + boff, 0.f);
        gemm62<EPI_BIASR, false>(sW1, LDW, sFrT, LDT, DIM, DIM, sKt, LDQ, bk1 + boff, 0.f);
        __syncthreads();

        // step3: logits1
        gemm62<EPI_SCALE, true>(sQt, LDQ, sKt, LDQ, S, DIM, sS, LDQ, 0, scale);
        __syncthreads();

        // step4: softmax1 -> A1t
        softmax62t(sS, sA1t);

        // step5: dir2 weights ready; prefetch dir1(h+1); both dir2 projections
        cp_wait0();
        __syncthreads();
        if (h + 1 < H) {
            prefetch_w(Wq1 + woff + DIM * DIM, sW0);
            prefetch_w(Wk1 + woff + DIM * DIM, sW1);
        }
        gemm62<EPI_BIASR, false>(sW2, LDW, sFrT, LDT, DIM, DIM, sQt, LDQ, bq2 + boff, 0.f);
        gemm62<EPI_BIASR, false>(sW3, LDW, sFnT, LDT, DIM, DIM, sKt, LDQ, bk2 + boff, 0.f);
        __syncthreads();

        // step6: logits2
        gemm62<EPI_SCALE, true>(sQt, LDQ, sKt, LDQ, S, DIM, sS, LDQ, 0, scale);
        __syncthreads();

        // step7: softmax2 -> A2t
        softmax62t(sS, sA2t);
        __syncthreads();

        // step8: loss + both output GEMMs (sO1/sO2 alias sQt/sKt)
        float ss = gemm62<EPI_LOSS, true>(sA1t, LDA1, sA2t, LDA1, S, S, 0, 0, 0, 0.f);
        gemm62<EPI_PLAIN, true>(sFr, LDF, sA1t, LDA1, DIM, S, sQt, LDQ, 0, 0.f);
        gemm62<EPI_PLAIN, true>(sFn, LDF, sA2t, LDA1, DIM, S, sKt, LDQ, 0, 0.f);
#pragma unroll
        for (int off = 16; off; off >>= 1) ss += __shfl_xor_sync(0xffffffffu, ss, off);
        if ((tid & 31) == 0) swarp[tid >> 5] = ss;
        __syncthreads();

        // step9: gated coalesced output copy + norm
        float* o1 = out + ((size_t)(b * H + h) * 124) * DIM;
        float* o2 = o1 + (size_t)S * DIM;
        copy_out(sQt, sg, o1, false);
        copy_out(sKt, sg, o2, true);
        if (tid == 0) {
            float t = 0.f;
#pragma unroll
            for (int w = 0; w < 16; w++) t += swarp[w];
            g_norms[b * H + h] = sqrtf(t);
        }
        // next head's step1 barrier protects sQt/sKt reuse
    }
}

__global__ void loss_kernel(float* __restrict__ out_loss)
{
    __shared__ float ws[8];
    const int tid = threadIdx.x;
    float s = 0.f;
    for (int i = tid; i < BSZ * H; i += 256) s += g_norms[i];
#pragma unroll
    for (int off = 16; off; off >>= 1) s += __shfl_xor_sync(0xffffffffu, s, off);
    if ((tid & 31) == 0) ws[tid >> 5] = s;
    __syncthreads();
    if (tid == 0) {
        float t = 0.f;
#pragma unroll
        for (int w = 0; w < 8; w++) t += ws[w];
        *out_loss = t / (float)(BSZ * H);
    }
}

extern "C" void kernel_launch(void* const* d_in, const int* in_sizes, int n_in,
                              void* d_out, int out_size)
{
    const float* Fn  = (const float*)d_in[0];
    const float* Fr  = (const float*)d_in[1];
    const float* Wq1 = (const float*)d_in[2];
    const float* bq1 = (const float*)d_in[3];
    const float* Wk1 = (const float*)d_in[4];
    const float* bk1 = (const float*)d_in[5];
    const float* Wq2 = (const float*)d_in[6];
    const float* bq2 = (const float*)d_in[7];
    const float* Wk2 = (const float*)d_in[8];
    const float* bk2 = (const float*)d_in[9];
    const float* Wg  = (const float*)d_in[10];
    const float* bg  = (const float*)d_in[11];
    float* out = (float*)d_out;

    const int smem_bytes = SMEM_FLOATS * (int)sizeof(float);
    cudaFuncSetAttribute(fused_kernel, cudaFuncAttributeMaxDynamicSharedMemorySize, smem_bytes);
    fused_kernel<<<BSZ, NT, smem_bytes>>>(Fn, Fr, Wq1, bq1, Wk1, bk1,
                                          Wq2, bq2, Wk2, bk2, Wg, bg, out);
    loss_kernel<<<1, 256>>>(out + (size_t)out_size - 1);
}

// round 5
// speedup vs baseline: 1.5502x; 1.1050x over previous
#include <cuda_runtime.h>
#include <cstdint>

// ---------------------------------------------------------------------------
// DualOrthogonalAttention fused kernel, round 5: crossbar-optimized.
// - All B operands: stride 64 (2 wavefronts/row); transposed buffers XOR-
//   swizzled so writes are ~2-way instead of 32-way conflicted.
// - A operands loaded as float4 k-quads (half the wavefronts).
// - Output GEMMs row-major with gate folded into epilogue -> direct gmem
//   store; copy_out eliminated. Col d=64 computed inside softmax (warp dot).
// ---------------------------------------------------------------------------

#define BSZ 1024
#define S 62
#define DIM 65
#define H 10
#define NT 512
#define LDW 68          // weight tiles [65 x 65], stride mult-of-4, 16B-aligned rows

#define SWZ(k) (((k) & 15) << 1)

// smem offsets (floats)
#define OFF_FN64 0                         // [62 x 64]
#define OFF_FNC  (OFF_FN64 + 3968)         // [64]  (col d=64 of Fn)
#define OFF_FR64 (OFF_FNC + 64)            // [62 x 64]
#define OFF_FRC  (OFF_FR64 + 3968)         // [64]
#define OFF_FNT  (OFF_FRC + 64)            // [65 x 64] swizzled FnT
#define OFF_FRT  (OFF_FNT + 4160)          // [65 x 64] swizzled FrT
#define OFF_QT   (OFF_FRT + 4160)          // [65 x 64]
#define OFF_KT   (OFF_QT + 4160)           // [65 x 64]
#define OFF_A1   (OFF_KT + 4160)           // [62 x 64] row-major
#define OFF_A2   (OFF_A1 + 3968)           // [62 x 64] row-major
#define OFF_A2T  (OFF_A2 + 3968)           // [62 x 64] swizzled A2^T
#define OFF_W0   (OFF_A2T + 3968)          // [65 x 68]  (sS aliases first 3968)
#define OFF_W1   (OFF_W0 + 4420)
#define OFF_W2   (OFF_W1 + 4420)
#define OFF_W3   (OFF_W2 + 4420)
#define OFF_G1   (OFF_W3 + 4420)           // gate g [65]
#define OFF_G2   (OFF_G1 + 68)             // 1 - g  [65]
#define OFF_MEAN (OFF_G2 + 68)             // [130]
#define OFF_WARP (OFF_MEAN + 132)
#define SMEM_FLOATS (OFF_WARP + 20)        // 54576 floats = 213.2 KB

__device__ float g_norms[BSZ * H];

// ---------------------------------------------------------------------------
__device__ __forceinline__ void cp_async4(uint32_t dst, const float* src) {
    asm volatile("cp.async.ca.shared.global [%0], [%1], 4;\n" :: "r"(dst), "l"(src));
}
__device__ __forceinline__ void cp_commit() {
    asm volatile("cp.async.commit_group;\n" ::);
}
__device__ __forceinline__ void cp_wait0() {
    asm volatile("cp.async.wait_group 0;\n" ::);
}

__device__ __forceinline__ void prefetch_w(const float* __restrict__ gW, float* sW) {
    uint32_t base = (uint32_t)__cvta_generic_to_shared(sW);
    for (int idx = threadIdx.x; idx < DIM * DIM; idx += NT) {
        const int row = idx / DIM;
        const int col = idx - row * DIM;
        cp_async4(base + (uint32_t)(row * LDW + col) * 4u, gW + idx);
    }
    cp_commit();
}

// ---------------------------------------------------------------------------
// C[m,j] = sum_k a(m,k) * B[k][j], B stride 64 (optionally swizzled rows).
// AKM: A[k*lda + m] (k-major); else A[m*lda + k] (row-major). A via float4.
// ---------------------------------------------------------------------------
#define EPI_BIASR 0   // C[m*64+j] = acc + bias[m]
#define EPI_SCALE 1   // C[m*64+j] = acc * scale
#define EPI_LOSS  2   // return sum (acc - I)^2
#define EPI_GATE  3   // gmem C[m*65+j] = gate[j]*acc   (all 32 lanes, N=64)

template <int EPI, bool AKM, bool BSWZ, int NR>
__device__ __forceinline__ float gemm_body(
    const float* __restrict__ A, const int lda,
    const float* __restrict__ Bt,
    const int r0, const int M, const int Kd,
    float* __restrict__ C,
    const float* __restrict__ aux, const float scale)
{
    const int lane = threadIdx.x & 31;
    const int j = lane << 1;
    float ss = 0.f;
    if (EPI != EPI_GATE && j >= S) return 0.f;

    float acc[NR][2];
#pragma unroll
    for (int i = 0; i < NR; i++) { acc[i][0] = 0.f; acc[i][1] = 0.f; }

    int k = 0;
#pragma unroll 4
    for (; k + 4 <= Kd; k += 4) {
        float2 b[4];
#pragma unroll
        for (int q = 0; q < 4; q++) {
            const int jj = BSWZ ? (j ^ SWZ(k + q)) : j;
            b[q] = *(const float2*)(Bt + ((k + q) << 6) + jj);
        }
        float a4[NR][4];
        if (AKM) {
            // a(k+q, r0+i): float4 covers rows r0..r0+3 at depth k+q
            float4 t0 = *(const float4*)(A + (k + 0) * lda + r0);
            float4 t1 = *(const float4*)(A + (k + 1) * lda + r0);
            float4 t2 = *(const float4*)(A + (k + 2) * lda + r0);
            float4 t3 = *(const float4*)(A + (k + 3) * lda + r0);
            a4[0][0] = t0.x; a4[1][0] = t0.y; a4[2][0] = t0.z; a4[3][0] = t0.w;
            a4[0][1] = t1.x; a4[1][1] = t1.y; a4[2][1] = t1.z; a4[3][1] = t1.w;
            a4[0][2] = t2.x; a4[1][2] = t2.y; a4[2][2] = t2.z; a4[3][2] = t2.w;
            a4[0][3] = t3.x; a4[1][3] = t3.y; a4[2][3] = t3.z; a4[3][3] = t3.w;
            if (NR == 5) {
#pragma unroll
                for (int q = 0; q < 4; q++) a4[NR - 1][q] = A[(k + q) * lda + r0 + 4];
            }
        } else {
#pragma unroll
            for (int i = 0; i < NR; i++) {
                const float4 t = *(const float4*)(A + (r0 + i) * lda + k);
                a4[i][0] = t.x; a4[i][1] = t.y; a4[i][2] = t.z; a4[i][3] = t.w;
            }
        }
#pragma unroll
        for (int q = 0; q < 4; q++) {
#pragma unroll
            for (int i = 0; i < NR; i++) {
                acc[i][0] = fmaf(a4[i][q], b[q].x, acc[i][0]);
                acc[i][1] = fmaf(a4[i][q], b[q].y, acc[i][1]);
            }
        }
    }
    for (; k < Kd; k++) {
        const int jj = BSWZ ? (j ^ SWZ(k)) : j;
        const float2 b = *(const float2*)(Bt + (k << 6) + jj);
#pragma unroll
        for (int i = 0; i < NR; i++) {
            const float x = AKM ? A[k * lda + r0 + i] : A[(r0 + i) * lda + k];
            acc[i][0] = fmaf(x, b.x, acc[i][0]);
            acc[i][1] = fmaf(x, b.y, acc[i][1]);
        }
    }

#pragma unroll
    for (int i = 0; i < NR; i++) {
        const int m = r0 + i;
        if (m < M) {
            if (EPI == EPI_BIASR) {
                const float bb = aux[m];
                *(float2*)(C + (m << 6) + j) = make_float2(acc[i][0] + bb, acc[i][1] + bb);
            } else if (EPI == EPI_SCALE) {
                *(float2*)(C + (m << 6) + j) = make_float2(acc[i][0] * scale, acc[i][1] * scale);
            } else if (EPI == EPI_GATE) {
                C[m * DIM + j]     = aux[j] * acc[i][0];
                C[m * DIM + j + 1] = aux[j + 1] * acc[i][1];
            } else {
                const float d0 = acc[i][0] - ((m == j) ? 1.f : 0.f);
                const float d1 = acc[i][1] - ((m == j + 1) ? 1.f : 0.f);
                ss = fmaf(d0, d0, ss); ss = fmaf(d1, d1, ss);
            }
        }
    }
    return ss;
}

template <int EPI, bool AKM, bool BSWZ>
__device__ __forceinline__ float gemm62(
    const float* __restrict__ A, const int lda,
    const float* __restrict__ Bt,
    const int M, const int Kd,
    float* __restrict__ C,
    const float* __restrict__ aux, const float scale)
{
    const int warp = threadIdx.x >> 5;
    if (M == DIM && warp == 15)
        return gemm_body<EPI, AKM, BSWZ, 5>(A, lda, Bt, 60, M, Kd, C, aux, scale);
    return gemm_body<EPI, AKM, BSWZ, 4>(A, lda, Bt, warp << 2, M, Kd, C, aux, scale);
}

// ---------------------------------------------------------------------------
// Row softmax over sS [62 x 64]. Writes row-major Arm; optionally swizzled
// transposed At. Also computes the d=64 output column: gcol[r*65] =
// gv * dot(softmax_row_r, tail).
// ---------------------------------------------------------------------------
__device__ __forceinline__ void softmax62(const float* __restrict__ sS,
                                          float* __restrict__ Arm,
                                          float* __restrict__ At,
                                          const float* __restrict__ tail,
                                          const float gv,
                                          float* __restrict__ gcol)
{
    const int warp = threadIdx.x >> 5;
    const int lane = threadIdx.x & 31;
    const bool ok0 = lane < S;
    const bool ok1 = lane + 32 < S;
    for (int r = warp; r < S; r += 16) {
        const float* row = sS + (r << 6);
        const float v0 = ok0 ? row[lane] : -1e30f;
        const float v1 = ok1 ? row[lane + 32] : -1e30f;
        float m = fmaxf(v0, v1);
#pragma unroll
        for (int off = 16; off; off >>= 1) m = fmaxf(m, __shfl_xor_sync(0xffffffffu, m, off));
        const float e0 = ok0 ? __expf(v0 - m) : 0.f;
        const float e1 = ok1 ? __expf(v1 - m) : 0.f;
        float s = e0 + e1;
#pragma unroll
        for (int off = 16; off; off >>= 1) s += __shfl_xor_sync(0xffffffffu, s, off);
        const float inv = 1.0f / s;
        const float a0 = e0 * inv;
        const float a1 = e1 * inv;
        if (ok0) Arm[(r << 6) + lane] = a0;
        if (ok1) Arm[(r << 6) + lane + 32] = a1;
        if (At) {
            if (ok0) At[(lane << 6) + (r ^ SWZ(lane))] = a0;
            if (ok1) At[((lane + 32) << 6) + (r ^ SWZ(lane + 32))] = a1;
        }
        // d=64 output column
        float d = a0 * (ok0 ? tail[lane] : 0.f) + a1 * (ok1 ? tail[lane + 32] : 0.f);
#pragma unroll
        for (int off = 16; off; off >>= 1) d += __shfl_xor_sync(0xffffffffu, d, off);
        if (lane == 0) gcol[r * DIM] = gv * d;
    }
}

__global__ void __launch_bounds__(NT, 1)
fused_kernel(const float* __restrict__ Fn, const float* __restrict__ Fr,
             const float* __restrict__ Wq1, const float* __restrict__ bq1,
             const float* __restrict__ Wk1, const float* __restrict__ bk1,
             const float* __restrict__ Wq2, const float* __restrict__ bq2,
             const float* __restrict__ Wk2, const float* __restrict__ bk2,
             const float* __restrict__ Wg, const float* __restrict__ bg,
             float* __restrict__ out)
{
    extern __shared__ float sm[];
    const int tid = threadIdx.x;
    const int b = blockIdx.x;

    float* sFn64 = sm + OFF_FN64;
    float* sFnC  = sm + OFF_FNC;
    float* sFr64 = sm + OFF_FR64;
    float* sFrC  = sm + OFF_FRC;
    float* sFnT  = sm + OFF_FNT;
    float* sFrT  = sm + OFF_FRT;
    float* sQt   = sm + OFF_QT;
    float* sKt   = sm + OFF_KT;
    float* sA1   = sm + OFF_A1;
    float* sA2   = sm + OFF_A2;
    float* sA2t  = sm + OFF_A2T;
    float* sW0   = sm + OFF_W0;
    float* sW1   = sm + OFF_W1;
    float* sW2   = sm + OFF_W2;
    float* sW3   = sm + OFF_W3;
    float* sS    = sW0;                 // alias: sS live only while W0 is free
    float* sg1   = sm + OFF_G1;
    float* sg2   = sm + OFF_G2;
    float* smean = sm + OFF_MEAN;
    float* swarp = sm + OFF_WARP;

    prefetch_w(Wq1, sW0);
    prefetch_w(Wk1, sW1);

    // load features into row-major(64)+tail and swizzled-transposed layouts
    for (int idx = tid; idx < S * DIM; idx += NT) {
        const int i = idx / DIM;
        const int d = idx - i * DIM;
        const float vn = Fn[(size_t)b * S * DIM + idx];
        const float vr = Fr[(size_t)b * S * DIM + idx];
        if (d < 64) { sFn64[(i << 6) + d] = vn; sFr64[(i << 6) + d] = vr; }
        else        { sFnC[i] = vn; sFrC[i] = vr; }
        const int ii = i ^ SWZ(d);
        sFnT[(d << 6) + ii] = vn;
        sFrT[(d << 6) + ii] = vr;
    }
    __syncthreads();

    // gate
    if (tid < 2 * DIM) {
        const int d = (tid < DIM) ? tid : tid - DIM;
        float s = 0.f;
        if (d < 64) {
            const float* src = (tid < DIM) ? sFn64 : sFr64;
            for (int i = 0; i < S; i++) s += src[(i << 6) + d];
        } else {
            const float* src = (tid < DIM) ? sFnC : sFrC;
            for (int i = 0; i < S; i++) s += src[i];
        }
        smean[tid] = s * (1.0f / (float)S);
    }
    __syncthreads();
    if (tid < DIM) {
        float acc = bg[tid];
        const float* wr = Wg + tid * 2 * DIM;
#pragma unroll 10
        for (int c = 0; c < 2 * DIM; c++) acc = fmaf(wr[c], smean[c], acc);
        const float g = 1.0f / (1.0f + __expf(-acc));
        sg1[tid] = g;
        sg2[tid] = 1.0f - g;
    }

    const float scale = rsqrtf((float)DIM);

    for (int h = 0; h < H; h++) {
        const int woff = h * DIM * DIM;
        const int boff = h * DIM;
        float* o1 = out + ((size_t)(b * H + h) * 124) * DIM;
        float* o2 = o1 + (size_t)S * DIM;

        // step1: W0/W1 ready (and prior-head smem reads complete)
        cp_wait0();
        __syncthreads();

        // step2: prefetch dir2 weights; dir1 projections
        prefetch_w(Wq2 + woff, sW2);
        prefetch_w(Wk2 + woff, sW3);
        gemm62<EPI_BIASR, false, true>(sW0, LDW, sFnT, DIM, DIM, sQt, bq1 + boff, 0.f);
        gemm62<EPI_BIASR, false, true>(sW1, LDW, sFrT, DIM, DIM, sKt, bk1 + boff, 0.f);
        __syncthreads();

        // step3: logits1 (sS aliases W0 — weights consumed in step2)
        gemm62<EPI_SCALE, true, false>(sQt, 64, sKt, S, DIM, sS, 0, scale);
        __syncthreads();

        // step4: softmax1 -> A1 row-major; also writes out_n col 64
        softmax62(sS, sA1, 0, sFrC, sg1[64], o1 + 64);

        // step5: dir2 weights ready; dir2 projections
        cp_wait0();
        __syncthreads();
        gemm62<EPI_BIASR, false, true>(sW2, LDW, sFrT, DIM, DIM, sQt, bq2 + boff, 0.f);
        gemm62<EPI_BIASR, false, true>(sW3, LDW, sFnT, DIM, DIM, sKt, bk2 + boff, 0.f);
        __syncthreads();

        // step6: logits2
        gemm62<EPI_SCALE, true, false>(sQt, 64, sKt, S, DIM, sS, 0, scale);
        __syncthreads();

        // step7: softmax2 -> A2 row-major + swizzled A2t; out_r col 64
        softmax62(sS, sA2, sA2t, sFnC, sg2[64], o2 + 64);
        __syncthreads();

        // step8: refill W0/W1 for next head; loss + gated output GEMMs
        if (h + 1 < H) {
            prefetch_w(Wq1 + woff + DIM * DIM, sW0);
            prefetch_w(Wk1 + woff + DIM * DIM, sW1);
        }
        float ss = gemm62<EPI_LOSS, false, true>(sA1, 64, sA2t, S, S, 0, 0, 0.f);
        gemm62<EPI_GATE, false, false>(sA1, 64, sFr64, S, S, o1, sg1, 0.f);
        gemm62<EPI_GATE, false, false>(sA2, 64, sFn64, S, S, o2, sg2, 0.f);
#pragma unroll
        for (int off = 16; off; off >>= 1) ss += __shfl_xor_sync(0xffffffffu, ss, off);
        if ((tid & 31) == 0) swarp[tid >> 5] = ss;
        __syncthreads();
        if (tid == 0) {
            float t = 0.f;
#pragma unroll
            for (int w = 0; w < 16; w++) t += swarp[w];
            g_norms[b * H + h] = sqrtf(t);
        }
    }
}

__global__ void loss_kernel(float* __restrict__ out_loss)
{
    __shared__ float ws[8];
    const int tid = threadIdx.x;
    float s = 0.f;
    for (int i = tid; i < BSZ * H; i += 256) s += g_norms[i];
#pragma unroll
    for (int off = 16; off; off >>= 1) s += __shfl_xor_sync(0xffffffffu, s, off);
    if ((tid & 31) == 0) ws[tid >> 5] = s;
    __syncthreads();
    if (tid == 0) {
        float t = 0.f;
#pragma unroll
        for (int w = 0; w < 8; w++) t += ws[w];
        *out_loss = t / (float)(BSZ * H);
    }
}

extern "C" void kernel_launch(void* const* d_in, const int* in_sizes, int n_in,
                              void* d_out, int out_size)
{
    const float* Fn  = (const float*)d_in[0];
    const float* Fr  = (const float*)d_in[1];
    const float* Wq1 = (const float*)d_in[2];
    const float* bq1 = (const float*)d_in[3];
    const float* Wk1 = (const float*)d_in[4];
    const float* bk1 = (const float*)d_in[5];
    const float* Wq2 = (const float*)d_in[6];
    const float* bq2 = (const float*)d_in[7];
    const float* Wk2 = (const float*)d_in[8];
    const float* bk2 = (const float*)d_in[9];
    const float* Wg  = (const float*)d_in[10];
    const float* bg  = (const float*)d_in[11];
    float* out = (float*)d_out;

    const int smem_bytes = SMEM_FLOATS * (int)sizeof(float);
    cudaFuncSetAttribute(fused_kernel, cudaFuncAttributeMaxDynamicSharedMemorySize, smem_bytes);
    fused_kernel<<<BSZ, NT, smem_bytes>>>(Fn, Fr, Wq1, bq1, Wk1, bk1,
                                          Wq2, bq2, Wk2, bk2, Wg, bg, out);
    loss_kernel<<<1, 256>>>(out + (size_t)out_size - 1);
}